// round 1
// baseline (speedup 1.0000x reference)
#include <cuda_runtime.h>
#include <cstdint>
#include <cstddef>

// Problem constants
#define BB   8
#define HH   128
#define WW   128
#define CIN  64
#define GG   2
#define GC   32
#define KK   3
#define TAPS 9
#define SC   288      // KK*KK*GC
#define GF   64
#define HW   (HH*WW)          // 16384
#define NBG  (BB*GG)          // 16

// Static device scratch (allocation-free contract: __device__ globals)
__device__ __align__(16) float g_off [(size_t)NBG * HW * 18];   //  ~18 MiB
__device__ __align__(16) float g_samp[(size_t)NBG * HW * SC];   // ~302 MiB
__device__ __align__(16) float g_dw  [(size_t)NBG * HW * SC];   // ~302 MiB

// ---------------------------------------------------------------------------
// K1: offset conv — 3x3, GC(32) -> 18, SAME zero padding, per group.
// One thread = one (b,g,h,w) pixel, computes all 18 offset channels.
// ---------------------------------------------------------------------------
__global__ __launch_bounds__(256) void k_offsets(
    const float* __restrict__ x,
    const float* __restrict__ off_w,
    const float* __restrict__ off_b)
{
    __shared__ float ws[9 * 32 * 20];  // [dydx][c][o padded to 20]

    int id = blockIdx.x * 256 + threadIdx.x;         // (bg*HW + p)
    int bg = id >> 14;                                // /16384 (uniform per block)
    int g  = bg & 1;
    int b  = bg >> 1;
    int p  = id & (HW - 1);
    int h  = p >> 7, w = p & 127;

    // Stage off_w[g] into smem, padded to 20 outputs for float4 reads.
    for (int i = threadIdx.x; i < 9 * 32 * 20; i += 256) {
        int o  = i % 20;
        int rc = i / 20;              // dydx*32 + c
        float v = 0.f;
        if (o < 18) {
            int c = rc & 31;
            int dydx = rc >> 5;
            v = off_w[(g * 9 + dydx) * (32 * 18) + c * 18 + o];
        }
        ws[i] = v;
    }
    __syncthreads();

    float acc[20];
#pragma unroll
    for (int q = 0; q < 20; q++) acc[q] = 0.f;

    for (int dy = 0; dy < 3; dy++) {
        int yy = h + dy - 1;
        if ((unsigned)yy >= (unsigned)HH) continue;
        for (int dx = 0; dx < 3; dx++) {
            int xx = w + dx - 1;
            if ((unsigned)xx >= (unsigned)WW) continue;
            const float* xp = x + (((size_t)b * HH + yy) * WW + xx) * CIN + g * GC;
            const float* wp = ws + (dy * 3 + dx) * 32 * 20;
#pragma unroll 4
            for (int c = 0; c < 32; c++) {
                float xv = __ldg(xp + c);
                const float4* w4 = (const float4*)(wp + c * 20);
#pragma unroll
                for (int q = 0; q < 5; q++) {
                    float4 wv = w4[q];
                    acc[q * 4 + 0] += xv * wv.x;
                    acc[q * 4 + 1] += xv * wv.y;
                    acc[q * 4 + 2] += xv * wv.z;
                    acc[q * 4 + 3] += xv * wv.w;
                }
            }
        }
    }

    float* op = g_off + (size_t)id * 18;
#pragma unroll
    for (int o = 0; o < 18; o++)
        op[o] = acc[o] + __ldg(off_b + g * 18 + o);
}

// ---------------------------------------------------------------------------
// K2: bilinear sampling. One thread = one (bg, pixel, tap, c4) -> float4.
// Replicates reference boundary semantics: locs clipped to [0, 127]; when a
// coordinate lands exactly on 127.0, both sub-weights become 0 -> sample 0.
// ---------------------------------------------------------------------------
__global__ __launch_bounds__(256) void k_sample(const float* __restrict__ x)
{
    int id = blockIdx.x * 256 + threadIdx.x;     // ((bg*HW+p)*9 + t)*8 + c4
    int c4 = id & 7;
    int u  = id >> 3;
    int t  = u % 9;
    int v  = u / 9;                               // bg*HW + p
    int p  = v & (HW - 1);
    int bg = v >> 14;
    int g  = bg & 1, b = bg >> 1;
    int h  = p >> 7, w = p & 127;

    const float* offp = g_off + (size_t)v * 18 + 2 * t;
    float lx = (float)(w + (t % 3) - 1) + offp[0];
    float ly = (float)(h + (t / 3) - 1) + offp[1];
    lx = fminf(fmaxf(lx, 0.f), 127.f);
    ly = fminf(fmaxf(ly, 0.f), 127.f);

    float fx = floorf(lx), fy = floorf(ly);
    int   x0 = (int)fx,    y0 = (int)fy;
    float x1f = fminf(fx + 1.f, 127.f);
    float y1f = fminf(fy + 1.f, 127.f);
    int   x1 = (int)x1f,   y1 = (int)y1f;

    float wxl = x1f - lx, wxh = lx - fx;   // weight for x0 col, x1 col
    float wyl = y1f - ly, wyh = ly - fy;   // weight for y0 row, y1 row

    const float* base = x + (size_t)b * HW * CIN + g * GC + c4 * 4;
    float4 Ia = *(const float4*)(base + (y0 * WW + x0) * CIN);
    float4 Ib = *(const float4*)(base + (y1 * WW + x0) * CIN);
    float4 Ic = *(const float4*)(base + (y0 * WW + x1) * CIN);
    float4 Id = *(const float4*)(base + (y1 * WW + x1) * CIN);

    float wa = wxl * wyl, wbw = wxl * wyh, wc = wxh * wyl, wd = wxh * wyh;
    float4 r;
    r.x = wa * Ia.x + wbw * Ib.x + wc * Ic.x + wd * Id.x;
    r.y = wa * Ia.y + wbw * Ib.y + wc * Ic.y + wd * Id.y;
    r.z = wa * Ia.z + wbw * Ib.z + wc * Ic.z + wd * Id.z;
    r.w = wa * Ia.w + wbw * Ib.w + wc * Ic.w + wd * Id.w;

    *(float4*)(g_samp + (size_t)v * SC + t * GC + c4 * 4) = r;
}

// ---------------------------------------------------------------------------
// K3: depthwise 3x3 over the 288 sampled channels (SAME, zero pad).
// One thread = one (bg, pixel, sc4) -> float4.
// Weight: dw_w[g, dy, dx, sc, 0]  (transpose in reference makes it per-channel)
// ---------------------------------------------------------------------------
__global__ __launch_bounds__(256) void k_dw(
    const float* __restrict__ dw_w,
    const float* __restrict__ dw_b)
{
    int id  = blockIdx.x * 256 + threadIdx.x;   // (bg*HW+p)*72 + sc4
    int sc4 = id % 72;
    int q   = id / 72;                           // bg*HW + p
    int p   = q & (HW - 1);
    int bg  = q >> 14;
    int g   = bg & 1;
    int h   = p >> 7, w = p & 127;

    float4 acc = __ldg((const float4*)(dw_b + g * SC + sc4 * 4));
    const float* srcb = g_samp + (size_t)bg * HW * SC + sc4 * 4;
    const float* wb   = dw_w + g * 9 * SC + sc4 * 4;

#pragma unroll
    for (int dy = 0; dy < 3; dy++) {
        int yy = h + dy - 1;
        if ((unsigned)yy >= (unsigned)HH) continue;
#pragma unroll
        for (int dx = 0; dx < 3; dx++) {
            int xx = w + dx - 1;
            if ((unsigned)xx >= (unsigned)WW) continue;
            float4 s  = *(const float4*)(srcb + (size_t)(yy * WW + xx) * SC);
            float4 wk = __ldg((const float4*)(wb + (dy * 3 + dx) * SC));
            acc.x += s.x * wk.x;
            acc.y += s.y * wk.y;
            acc.z += s.z * wk.z;
            acc.w += s.w * wk.w;
        }
    }
    *(float4*)(g_dw + (size_t)q * SC + sc4 * 4) = acc;
}

// ---------------------------------------------------------------------------
// K4: pointwise GEMM per (b,g): [16384 x 288] @ [288 x 64] + bias -> out.
// BM=128, BN=64, BK=32, 256 threads, 8x4 register tile per thread.
// Output layout: out[(b*HW + p)*128 + g*64 + f]
// ---------------------------------------------------------------------------
__global__ __launch_bounds__(256) void k_gemm(
    const float* __restrict__ pw_w,
    const float* __restrict__ pw_b,
    float* __restrict__ out)
{
    __shared__ float Ast[32][128];   // transposed A tile: [k][row]
    __shared__ float Bs [32][64];

    int bg   = blockIdx.y;
    int g    = bg & 1, b = bg >> 1;
    int row0 = blockIdx.x * 128;

    const float* A  = g_dw + (size_t)bg * HW * SC;
    const float* Wt = pw_w + g * SC * GF;

    int tid = threadIdx.x;
    int tx  = tid & 15;       // 0..15 -> 4 cols each
    int ty  = tid >> 4;       // 0..15 -> 8 rows each

    float acc[8][4];
#pragma unroll
    for (int i = 0; i < 8; i++)
#pragma unroll
        for (int j = 0; j < 4; j++) acc[i][j] = 0.f;

    for (int k0 = 0; k0 < SC; k0 += 32) {
        // Load A tile 128x32, store transposed
#pragma unroll
        for (int it = 0; it < 4; it++) {
            int idx = it * 256 + tid;
            int r   = idx >> 3;        // row 0..127
            int kq  = idx & 7;         // k-quad 0..7
            float4 vv = __ldg((const float4*)(A + (size_t)(row0 + r) * SC + k0 + kq * 4));
            Ast[kq * 4 + 0][r] = vv.x;
            Ast[kq * 4 + 1][r] = vv.y;
            Ast[kq * 4 + 2][r] = vv.z;
            Ast[kq * 4 + 3][r] = vv.w;
        }
        // Load B tile 32x64
#pragma unroll
        for (int it = 0; it < 2; it++) {
            int idx = it * 256 + tid;
            int r   = idx >> 4;        // k-row 0..31
            int c4  = idx & 15;
            float4 vv = __ldg((const float4*)(Wt + (k0 + r) * GF + c4 * 4));
            *(float4*)&Bs[r][c4 * 4] = vv;
        }
        __syncthreads();

#pragma unroll
        for (int kk = 0; kk < 32; kk++) {
            float4 b4 = *(const float4*)&Bs[kk][tx * 4];
            float4 a0 = *(const float4*)&Ast[kk][ty * 8];
            float4 a1 = *(const float4*)&Ast[kk][ty * 8 + 4];
            float av[8] = {a0.x, a0.y, a0.z, a0.w, a1.x, a1.y, a1.z, a1.w};
            float bv[4] = {b4.x, b4.y, b4.z, b4.w};
#pragma unroll
            for (int i = 0; i < 8; i++)
#pragma unroll
                for (int j = 0; j < 4; j++)
                    acc[i][j] += av[i] * bv[j];
        }
        __syncthreads();
    }

    float4 bias = __ldg((const float4*)(pw_b + g * GF + tx * 4));
#pragma unroll
    for (int i = 0; i < 8; i++) {
        int p = row0 + ty * 8 + i;
        float4 o;
        o.x = acc[i][0] + bias.x;
        o.y = acc[i][1] + bias.y;
        o.z = acc[i][2] + bias.z;
        o.w = acc[i][3] + bias.w;
        *(float4*)(out + ((size_t)b * HW + p) * (GG * GF) + g * GF + tx * 4) = o;
    }
}

// ---------------------------------------------------------------------------
extern "C" void kernel_launch(void* const* d_in, const int* in_sizes, int n_in,
                              void* d_out, int out_size)
{
    const float* x     = (const float*)d_in[0];
    const float* off_w = (const float*)d_in[1];
    const float* off_b = (const float*)d_in[2];
    const float* dw_w  = (const float*)d_in[3];
    const float* dw_b  = (const float*)d_in[4];
    const float* pw_w  = (const float*)d_in[5];
    const float* pw_b  = (const float*)d_in[6];
    float* out = (float*)d_out;

    // K1: offsets — 16 (b,g) slabs * 16384 pixels / 256
    k_offsets<<<NBG * HW / 256, 256>>>(x, off_w, off_b);
    // K2: bilinear sampling — NBG*HW*9*8 threads
    k_sample<<<(size_t)NBG * HW * 9 * 8 / 256, 256>>>(x);
    // K3: depthwise — NBG*HW*72 threads
    k_dw<<<(size_t)NBG * HW * 72 / 256, 256>>>(dw_w, dw_b);
    // K4: pointwise GEMM
    k_gemm<<<dim3(HW / 128, NBG), 256>>>(pw_w, pw_b, out);
}

// round 5
// speedup vs baseline: 1.0745x; 1.0745x over previous
#include <cuda_runtime.h>
#include <cstdint>
#include <cstddef>

// Problem constants
#define BB   8
#define HH   128
#define WW   128
#define CIN  64
#define GG   2
#define GC   32
#define KK   3
#define TAPS 9
#define SC   288      // KK*KK*GC
#define GF   64
#define HW   (HH*WW)          // 16384
#define NBG  (BB*GG)          // 16

// Static device scratch (allocation-free contract: __device__ globals)
__device__ __align__(16) float g_off [(size_t)NBG * HW * 18];   //  ~18 MiB
__device__ __align__(16) float g_samp[(size_t)NBG * HW * SC];   // ~302 MiB

// ---------------------------------------------------------------------------
// K1: offset conv — 3x3, GC(32) -> 18, SAME zero padding, per group.
// ---------------------------------------------------------------------------
__global__ __launch_bounds__(256) void k_offsets(
    const float* __restrict__ x,
    const float* __restrict__ off_w,
    const float* __restrict__ off_b)
{
    __shared__ float ws[9 * 32 * 20];  // [dydx][c][o padded to 20]

    int id = blockIdx.x * 256 + threadIdx.x;         // (bg*HW + p)
    int bg = id >> 14;
    int g  = bg & 1;
    int b  = bg >> 1;
    int p  = id & (HW - 1);
    int h  = p >> 7, w = p & 127;

    for (int i = threadIdx.x; i < 9 * 32 * 20; i += 256) {
        int o  = i % 20;
        int rc = i / 20;
        float v = 0.f;
        if (o < 18) {
            int c = rc & 31;
            int dydx = rc >> 5;
            v = off_w[(g * 9 + dydx) * (32 * 18) + c * 18 + o];
        }
        ws[i] = v;
    }
    __syncthreads();

    float acc[20];
#pragma unroll
    for (int q = 0; q < 20; q++) acc[q] = 0.f;

    for (int dy = 0; dy < 3; dy++) {
        int yy = h + dy - 1;
        if ((unsigned)yy >= (unsigned)HH) continue;
        for (int dx = 0; dx < 3; dx++) {
            int xx = w + dx - 1;
            if ((unsigned)xx >= (unsigned)WW) continue;
            const float* xp = x + (((size_t)b * HH + yy) * WW + xx) * CIN + g * GC;
            const float* wp = ws + (dy * 3 + dx) * 32 * 20;
#pragma unroll 4
            for (int c = 0; c < 32; c++) {
                float xv = __ldg(xp + c);
                const float4* w4 = (const float4*)(wp + c * 20);
#pragma unroll
                for (int q = 0; q < 5; q++) {
                    float4 wv = w4[q];
                    acc[q * 4 + 0] += xv * wv.x;
                    acc[q * 4 + 1] += xv * wv.y;
                    acc[q * 4 + 2] += xv * wv.z;
                    acc[q * 4 + 3] += xv * wv.w;
                }
            }
        }
    }

    float* op = g_off + (size_t)id * 18;
#pragma unroll
    for (int o = 0; o < 18; o++)
        op[o] = acc[o] + __ldg(off_b + g * 18 + o);
}

// ---------------------------------------------------------------------------
// K2: bilinear sampling. One thread = one (bg, pixel, tap, c4) -> float4.
// ---------------------------------------------------------------------------
__global__ __launch_bounds__(256) void k_sample(const float* __restrict__ x)
{
    int id = blockIdx.x * 256 + threadIdx.x;     // ((bg*HW+p)*9 + t)*8 + c4
    int c4 = id & 7;
    int u  = id >> 3;
    int t  = u % 9;
    int v  = u / 9;                               // bg*HW + p
    int p  = v & (HW - 1);
    int bg = v >> 14;
    int g  = bg & 1, b = bg >> 1;
    int h  = p >> 7, w = p & 127;

    const float* offp = g_off + (size_t)v * 18 + 2 * t;
    float lx = (float)(w + (t % 3) - 1) + offp[0];
    float ly = (float)(h + (t / 3) - 1) + offp[1];
    lx = fminf(fmaxf(lx, 0.f), 127.f);
    ly = fminf(fmaxf(ly, 0.f), 127.f);

    float fx = floorf(lx), fy = floorf(ly);
    int   x0 = (int)fx,    y0 = (int)fy;
    float x1f = fminf(fx + 1.f, 127.f);
    float y1f = fminf(fy + 1.f, 127.f);
    int   x1 = (int)x1f,   y1 = (int)y1f;

    float wxl = x1f - lx, wxh = lx - fx;
    float wyl = y1f - ly, wyh = ly - fy;

    const float* base = x + (size_t)b * HW * CIN + g * GC + c4 * 4;
    float4 Ia = *(const float4*)(base + (y0 * WW + x0) * CIN);
    float4 Ib = *(const float4*)(base + (y1 * WW + x0) * CIN);
    float4 Ic = *(const float4*)(base + (y0 * WW + x1) * CIN);
    float4 Id = *(const float4*)(base + (y1 * WW + x1) * CIN);

    float wa = wxl * wyl, wbw = wxl * wyh, wc = wxh * wyl, wd = wxh * wyh;
    float4 r;
    r.x = wa * Ia.x + wbw * Ib.x + wc * Ic.x + wd * Id.x;
    r.y = wa * Ia.y + wbw * Ib.y + wc * Ic.y + wd * Id.y;
    r.z = wa * Ia.z + wbw * Ib.z + wc * Ic.z + wd * Id.z;
    r.w = wa * Ia.w + wbw * Ib.w + wc * Ic.w + wd * Id.w;

    *(float4*)(g_samp + (size_t)v * SC + t * GC + c4 * 4) = r;
}

// ---------------------------------------------------------------------------
// K3 (fused): depthwise 3x3 + pointwise GEMM + bias. Dynamic smem (81 KB).
// Block = one image row (128 px) of one (b,g). M=128, N=64, K=288 (9 chunks
// of 32). Per chunk: stage 3-row g_samp band in smem, compute depthwise into
// transposed A-tile, accumulate register-tiled GEMM against pw_w chunk.
// ---------------------------------------------------------------------------
#define SS_STRIDE 36
#define SMEM_SSAMP_OFF 0                                        // 3*128*36 floats
#define SMEM_AST_OFF   (3 * 128 * SS_STRIDE)                    // 32*128
#define SMEM_BS_OFF    (SMEM_AST_OFF + 32 * 128)                // 32*64
#define SMEM_WDW_OFF   (SMEM_BS_OFF + 32 * 64)                  // 9*32
#define SMEM_FLOATS    (SMEM_WDW_OFF + 9 * 32)
#define SMEM_BYTES     (SMEM_FLOATS * 4)                        // 81024

__global__ __launch_bounds__(256) void k_dw_gemm(
    const float* __restrict__ dw_w,
    const float* __restrict__ dw_b,
    const float* __restrict__ pw_w,
    const float* __restrict__ pw_b,
    float* __restrict__ out)
{
    extern __shared__ float smem[];
    float* Ssamp = smem + SMEM_SSAMP_OFF;   // [3][128][36]
    float* Ast   = smem + SMEM_AST_OFF;     // [32][128]
    float* Bs    = smem + SMEM_BS_OFF;      // [32][64]
    float* Wdw   = smem + SMEM_WDW_OFF;     // [9][32]

    int h   = blockIdx.x;                // image row = M-tile
    int bg  = blockIdx.y;
    int g   = bg & 1, b = bg >> 1;

    int tid = threadIdx.x;
    int tx  = tid & 15;                  // GEMM: 4 cols each
    int ty  = tid >> 4;                  // GEMM: 8 rows each
    int px  = tid & 127;                 // dw: one pixel
    int cb  = (tid >> 7) * 16;           // dw: 16 channels

    const float* sampb = g_samp + (size_t)bg * HW * SC;
    const float* Wt    = pw_w + g * SC * GF;
    const float* dwW   = dw_w + g * 9 * SC;
    const float* dwB   = dw_b + g * SC;

    float acc[8][4];
#pragma unroll
    for (int i = 0; i < 8; i++)
#pragma unroll
        for (int j = 0; j < 4; j++) acc[i][j] = 0.f;

    for (int k0 = 0; k0 < SC; k0 += 32) {
        __syncthreads();   // previous chunk's consumers done

        // --- stage g_samp band: 3 rows x 128 px x 32 ch (zero-pad OOB rows)
#pragma unroll
        for (int it = 0; it < 12; it++) {
            int idx  = it * 256 + tid;           // 0..3071 float4s
            int r    = idx >> 10;
            int rem  = idx & 1023;
            int pl   = rem >> 3;
            int c4   = rem & 7;
            int yy   = h + r - 1;
            float4 v = make_float4(0.f, 0.f, 0.f, 0.f);
            if ((unsigned)yy < (unsigned)HH)
                v = *(const float4*)(sampb + ((size_t)(yy * WW + pl)) * SC + k0 + c4 * 4);
            *(float4*)&Ssamp[(r * 128 + pl) * SS_STRIDE + c4 * 4] = v;
        }
        // --- stage dw weights (9x32): strided — 288 entries, 256 threads
        for (int i = tid; i < 9 * 32; i += 256)
            Wdw[i] = dwW[(i >> 5) * SC + k0 + (i & 31)];
        // --- stage pw_w chunk (32x64)
#pragma unroll
        for (int it = 0; it < 2; it++) {
            int idx = it * 256 + tid;
            int r   = idx >> 4;
            int c4  = idx & 15;
            *(float4*)&Bs[r * 64 + c4 * 4] =
                __ldg((const float4*)(Wt + (k0 + r) * GF + c4 * 4));
        }
        __syncthreads();

        // --- depthwise: each thread -> 16 channels of one pixel
        {
            float dacc[16];
#pragma unroll
            for (int j = 0; j < 16; j++)
                dacc[j] = __ldg(dwB + k0 + cb + j);

#pragma unroll
            for (int dy = 0; dy < 3; dy++) {
#pragma unroll
                for (int dx = 0; dx < 3; dx++) {
                    int xx = px + dx - 1;
                    if ((unsigned)xx >= (unsigned)WW) continue;
                    const float* sp = &Ssamp[(dy * 128 + xx) * SS_STRIDE + cb];
                    const float* wp = &Wdw[(dy * 3 + dx) * 32 + cb];
#pragma unroll
                    for (int q = 0; q < 4; q++) {
                        float4 s  = *(const float4*)(sp + q * 4);
                        float4 wv = *(const float4*)(wp + q * 4);
                        dacc[q * 4 + 0] += s.x * wv.x;
                        dacc[q * 4 + 1] += s.y * wv.y;
                        dacc[q * 4 + 2] += s.z * wv.z;
                        dacc[q * 4 + 3] += s.w * wv.w;
                    }
                }
            }
#pragma unroll
            for (int j = 0; j < 16; j++)
                Ast[(cb + j) * 128 + px] = dacc[j];
        }
        __syncthreads();

        // --- GEMM accumulate over this 32-k chunk
#pragma unroll
        for (int kk = 0; kk < 32; kk++) {
            float4 b4 = *(const float4*)&Bs[kk * 64 + tx * 4];
            float4 a0 = *(const float4*)&Ast[kk * 128 + ty * 8];
            float4 a1 = *(const float4*)&Ast[kk * 128 + ty * 8 + 4];
            float av[8] = {a0.x, a0.y, a0.z, a0.w, a1.x, a1.y, a1.z, a1.w};
            float bv[4] = {b4.x, b4.y, b4.z, b4.w};
#pragma unroll
            for (int i = 0; i < 8; i++)
#pragma unroll
                for (int j = 0; j < 4; j++)
                    acc[i][j] += av[i] * bv[j];
        }
    }

    float4 bias = __ldg((const float4*)(pw_b + g * GF + tx * 4));
#pragma unroll
    for (int i = 0; i < 8; i++) {
        int p = h * WW + ty * 8 + i;
        float4 o;
        o.x = acc[i][0] + bias.x;
        o.y = acc[i][1] + bias.y;
        o.z = acc[i][2] + bias.z;
        o.w = acc[i][3] + bias.w;
        *(float4*)(out + ((size_t)b * HW + p) * (GG * GF) + g * GF + tx * 4) = o;
    }
}

// ---------------------------------------------------------------------------
extern "C" void kernel_launch(void* const* d_in, const int* in_sizes, int n_in,
                              void* d_out, int out_size)
{
    const float* x     = (const float*)d_in[0];
    const float* off_w = (const float*)d_in[1];
    const float* off_b = (const float*)d_in[2];
    const float* dw_w  = (const float*)d_in[3];
    const float* dw_b  = (const float*)d_in[4];
    const float* pw_w  = (const float*)d_in[5];
    const float* pw_b  = (const float*)d_in[6];
    float* out = (float*)d_out;

    // Opt-in to >48KB dynamic smem for the fused kernel. Host API, idempotent,
    // executes immediately (no graph node) — called unconditionally, no guards.
    cudaFuncSetAttribute(k_dw_gemm,
                         cudaFuncAttributeMaxDynamicSharedMemorySize,
                         SMEM_BYTES);

    k_offsets<<<NBG * HW / 256, 256>>>(x, off_w, off_b);
    k_sample<<<(size_t)NBG * HW * 9 * 8 / 256, 256>>>(x);
    k_dw_gemm<<<dim3(HH, NBG), 256, SMEM_BYTES>>>(dw_w, dw_b, pw_w, pw_b, out);
}